// round 17
// baseline (speedup 1.0000x reference)
#include <cuda_runtime.h>
#include <cuda_bf16.h>
#include <stdint.h>

#define NNODE 1000000
#define NEDGE 8000000

// Scratch in __device__ globals (zero-initialized at module load; g_deg is
// re-zeroed by k_final each run -> self-cleaning, no k_zero pass).
__device__ float  g_deg [NNODE];   // in-degree at dst; zeroed in k_final
__device__ float  g_dinv[NNODE];   // rsqrt(deg + 1)
__device__ float4 g_xs  [NNODE];   // x * dinv (gather source for scatter1)
__device__ float4 g_acc1[NNODE];   // layer-1 acc; INIT = xs (self-loop folded in)
__device__ float2 g_gs  [NNODE];   // (relu(.) W2) * dinv (gather source for scatter2)
__device__ float2 g_acc2[NNODE];   // layer-2 acc; INIT = gs (self-loop folded in)

// Weights in constant memory (LDCU uniform path — R15 win).
__constant__ float c_W1[256];   // [4,64] row-major
__constant__ float c_b1[64];
__constant__ float c_W2[128];   // [64,2] row-major

// ---------------------------------------------------------------------------
// PDL intrinsics
__device__ __forceinline__ void pdl_wait() {
    asm volatile("griddepcontrol.wait;" ::: "memory");
}
__device__ __forceinline__ void pdl_trigger() {
    asm volatile("griddepcontrol.launch_dependents;" ::: "memory");
}

__device__ __forceinline__ void red_v4(float4* p, float4 v) {
    asm volatile("red.global.add.v4.f32 [%0], {%1,%2,%3,%4};"
                 :: "l"(p), "f"(v.x), "f"(v.y), "f"(v.z), "f"(v.w) : "memory");
}
__device__ __forceinline__ void red_v2(float2* p, float2 v) {
    asm volatile("red.global.add.v2.f32 [%0], {%1,%2};"
                 :: "l"(p), "f"(v.x), "f"(v.y) : "memory");
}
__device__ __forceinline__ float4 ldcg_f4(const float4* p) { return __ldcg(p); }
__device__ __forceinline__ float2 ldcg_f2(const float2* p) { return __ldcg(p); }

// ---------------------------------------------------------------------------
// 1. in-degree at dst — 4 edges/thread
__global__ void __launch_bounds__(256) k_deg(const int* __restrict__ dst, int e) {
    pdl_wait();
    int base = (blockIdx.x * blockDim.x + threadIdx.x) * 4;
    if (base + 4 <= e) {
        int4 d = *(const int4*)(dst + base);
        atomicAdd(&g_deg[d.x], 1.0f);
        atomicAdd(&g_deg[d.y], 1.0f);
        atomicAdd(&g_deg[d.z], 1.0f);
        atomicAdd(&g_deg[d.w], 1.0f);
    } else {
        for (int i = base; i < e; i++) atomicAdd(&g_deg[dst[i]], 1.0f);
    }
    pdl_trigger();
}

// ---------------------------------------------------------------------------
// 2. dinv + pre-scaled features; acc1 INITIALIZED to xs (self-loop term)
__global__ void __launch_bounds__(256) k_prep(const float4* __restrict__ x, int n) {
    pdl_wait();
    int i = blockIdx.x * blockDim.x + threadIdx.x;
    if (i < n) {
        float di = rsqrtf(g_deg[i] + 1.0f);   // self-loop -> deg >= 1
        g_dinv[i] = di;
        float4 v = x[i];
        v.x *= di; v.y *= di; v.z *= di; v.w *= di;
        g_xs[i]   = v;
        g_acc1[i] = v;   // self-loop contribution pre-seeded
    }
    pdl_trigger();
}

// ---------------------------------------------------------------------------
// 3. layer-1 scatter: acc1[dst] += xs[src] — 4 edges/thread
__global__ void __launch_bounds__(256) k_scatter1(const int* __restrict__ src,
                                                  const int* __restrict__ dst, int e) {
    pdl_wait();
    int base = (blockIdx.x * blockDim.x + threadIdx.x) * 4;
    if (base + 4 <= e) {
        int4 s = *(const int4*)(src + base);
        int4 d = *(const int4*)(dst + base);
        float4 v0 = ldcg_f4(&g_xs[s.x]);
        float4 v1 = ldcg_f4(&g_xs[s.y]);
        float4 v2 = ldcg_f4(&g_xs[s.z]);
        float4 v3 = ldcg_f4(&g_xs[s.w]);
        red_v4(&g_acc1[d.x], v0);
        red_v4(&g_acc1[d.y], v1);
        red_v4(&g_acc1[d.z], v2);
        red_v4(&g_acc1[d.w], v3);
    } else {
        for (int i = base; i < e; i++)
            red_v4(&g_acc1[dst[i]], ldcg_f4(&g_xs[src[i]]));
    }
    pdl_trigger();
}

// ---------------------------------------------------------------------------
// 4. fused node transform — constant weights (LDCU), 4 nodes/thread to
//    amortize the 7 node-invariant weight loads per j over 4 nodes:
//    a4 = dinv * acc1; gs = (relu(a4 W1 + b1) W2) * dinv; acc2 = gs.
//    Per-node fma order identical to the reference.
__global__ void __launch_bounds__(256) k_mid(int nq) {   // nq = n/4
    pdl_wait();
    int i = blockIdx.x * blockDim.x + threadIdx.x;
    if (i >= nq) return;
    int i0 = 4 * i;

    float4 dd = *(const float4*)&g_dinv[i0];
    float4 aA = g_acc1[i0];
    float4 aB = g_acc1[i0 + 1];
    float4 aC = g_acc1[i0 + 2];
    float4 aD = g_acc1[i0 + 3];

    float a0A = dd.x * aA.x, a1A = dd.x * aA.y, a2A = dd.x * aA.z, a3A = dd.x * aA.w;
    float a0B = dd.y * aB.x, a1B = dd.y * aB.y, a2B = dd.y * aB.z, a3B = dd.y * aB.w;
    float a0C = dd.z * aC.x, a1C = dd.z * aC.y, a2C = dd.z * aC.z, a3C = dd.z * aC.w;
    float a0D = dd.w * aD.x, a1D = dd.w * aD.y, a2D = dd.w * aD.z, a3D = dd.w * aD.w;

    float o0A = 0.f, o1A = 0.f, o0B = 0.f, o1B = 0.f;
    float o0C = 0.f, o1C = 0.f, o0D = 0.f, o1D = 0.f;
#pragma unroll
    for (int j = 0; j < 64; j++) {
        float w0 = c_W1[j];
        float w1 = c_W1[64 + j];
        float w2 = c_W1[128 + j];
        float w3 = c_W1[192 + j];
        float bb = c_b1[j];
        float c0 = c_W2[2 * j];
        float c1 = c_W2[2 * j + 1];

        float hA = bb;
        hA = fmaf(a0A, w0, hA);
        hA = fmaf(a1A, w1, hA);
        hA = fmaf(a2A, w2, hA);
        hA = fmaf(a3A, w3, hA);
        hA = fmaxf(hA, 0.f);
        o0A = fmaf(hA, c0, o0A);
        o1A = fmaf(hA, c1, o1A);

        float hB = bb;
        hB = fmaf(a0B, w0, hB);
        hB = fmaf(a1B, w1, hB);
        hB = fmaf(a2B, w2, hB);
        hB = fmaf(a3B, w3, hB);
        hB = fmaxf(hB, 0.f);
        o0B = fmaf(hB, c0, o0B);
        o1B = fmaf(hB, c1, o1B);

        float hC = bb;
        hC = fmaf(a0C, w0, hC);
        hC = fmaf(a1C, w1, hC);
        hC = fmaf(a2C, w2, hC);
        hC = fmaf(a3C, w3, hC);
        hC = fmaxf(hC, 0.f);
        o0C = fmaf(hC, c0, o0C);
        o1C = fmaf(hC, c1, o1C);

        float hD = bb;
        hD = fmaf(a0D, w0, hD);
        hD = fmaf(a1D, w1, hD);
        hD = fmaf(a2D, w2, hD);
        hD = fmaf(a3D, w3, hD);
        hD = fmaxf(hD, 0.f);
        o0D = fmaf(hD, c0, o0D);
        o1D = fmaf(hD, c1, o1D);
    }
    float4 g01 = make_float4(o0A * dd.x, o1A * dd.x, o0B * dd.y, o1B * dd.y);
    float4 g23 = make_float4(o0C * dd.z, o1C * dd.z, o0D * dd.w, o1D * dd.w);

    *(float4*)&g_gs[i0]       = g01;   // four consecutive float2 -> two STG.128
    *(float4*)&g_gs[i0 + 2]   = g23;
    *(float4*)&g_acc2[i0]     = g01;   // self-loop contribution pre-seeded
    *(float4*)&g_acc2[i0 + 2] = g23;
    pdl_trigger();
}

// ---------------------------------------------------------------------------
// 5. layer-2 scatter: acc2[dst] += gs[src] — 4 edges/thread
__global__ void __launch_bounds__(256) k_scatter2(const int* __restrict__ src,
                                                  const int* __restrict__ dst, int e) {
    pdl_wait();
    int base = (blockIdx.x * blockDim.x + threadIdx.x) * 4;
    if (base + 4 <= e) {
        int4 s = *(const int4*)(src + base);
        int4 d = *(const int4*)(dst + base);
        float2 v0 = ldcg_f2(&g_gs[s.x]);
        float2 v1 = ldcg_f2(&g_gs[s.y]);
        float2 v2 = ldcg_f2(&g_gs[s.z]);
        float2 v3 = ldcg_f2(&g_gs[s.w]);
        red_v2(&g_acc2[d.x], v0);
        red_v2(&g_acc2[d.y], v1);
        red_v2(&g_acc2[d.z], v2);
        red_v2(&g_acc2[d.w], v3);
    } else {
        for (int i = base; i < e; i++)
            red_v2(&g_acc2[dst[i]], ldcg_f2(&g_gs[src[i]]));
    }
    pdl_trigger();
}

// ---------------------------------------------------------------------------
// 6. final: out = dinv * acc2 + b2 (acc2 already includes self-loop);
//    re-zeroes deg for the next run
__global__ void __launch_bounds__(256) k_final(const float* __restrict__ b2,
                                               float2* __restrict__ out, int n) {
    float bx = __ldg(&b2[0]);
    float by = __ldg(&b2[1]);
    pdl_wait();
    int i = blockIdx.x * blockDim.x + threadIdx.x;
    if (i < n) {
        float di = g_dinv[i];
        float2 a = g_acc2[i];
        out[i] = make_float2(di * a.x + bx, di * a.y + by);
        g_deg[i] = 0.0f;   // self-clean: ready for next invocation/replay
    }
}

// ---------------------------------------------------------------------------
// PDL launch helper
template <typename... Args>
static void pdl_launch(void (*kern)(Args...), int grid, int block,
                       Args... args) {
    cudaLaunchConfig_t cfg = {};
    cfg.gridDim  = dim3(grid, 1, 1);
    cfg.blockDim = dim3(block, 1, 1);
    cfg.dynamicSmemBytes = 0;
    cfg.stream = 0;
    cudaLaunchAttribute attr[1];
    attr[0].id = cudaLaunchAttributeProgrammaticStreamSerialization;
    attr[0].val.programmaticStreamSerializationAllowed = 1;
    cfg.attrs = attr;
    cfg.numAttrs = 1;
    cudaLaunchKernelEx(&cfg, kern, args...);
}

extern "C" void kernel_launch(void* const* d_in, const int* in_sizes, int n_in,
                              void* d_out, int out_size) {
    const float* x  = (const float*)d_in[0];   // [N,4]
    const int*   ei = (const int*)d_in[1];     // [2,E]  int32
    const float* W1 = (const float*)d_in[2];   // [4,64]
    const float* b1 = (const float*)d_in[3];   // [64]
    const float* W2 = (const float*)d_in[4];   // [64,2]
    const float* b2 = (const float*)d_in[5];   // [2]
    float2*      out = (float2*)d_out;         // [N,2]

    const int n = in_sizes[0] / 4;
    const int e = in_sizes[1] / 2;
    const int* src = ei;
    const int* dst = ei + e;

    // Stage weights into __constant__ (async D2D copies — graph-capturable,
    // no allocation). They complete before k_mid by stream order.
    cudaMemcpyToSymbolAsync(c_W1, W1, 256 * sizeof(float), 0,
                            cudaMemcpyDeviceToDevice, 0);
    cudaMemcpyToSymbolAsync(c_b1, b1, 64 * sizeof(float), 0,
                            cudaMemcpyDeviceToDevice, 0);
    cudaMemcpyToSymbolAsync(c_W2, W2, 128 * sizeof(float), 0,
                            cudaMemcpyDeviceToDevice, 0);

    const int T = 256;
    const int gn  = (n + T - 1) / T;
    const int gnq = (n / 4 + T - 1) / T;         // node quads (k_mid)
    const int ge4 = ((e + 3) / 4 + T - 1) / T;   // 4 edges/thread

    pdl_launch(k_deg,      ge4, T, dst, e);
    pdl_launch(k_prep,     gn,  T, (const float4*)x, n);
    pdl_launch(k_scatter1, ge4, T, src, dst, e);
    pdl_launch(k_mid,      gnq, T, n / 4);
    pdl_launch(k_scatter2, ge4, T, src, dst, e);
    pdl_launch(k_final,    gn,  T, b2, out, n);
}